// round 9
// baseline (speedup 1.0000x reference)
#include <cuda_runtime.h>
#include <cstdint>
#include <cstddef>

typedef unsigned long long ull;

#define B_ 128
#define I_ 64
#define S_ 2048
#define H_ 128
#define O_ 64
#define G4_ 512

// ---------------- scratch (allocation-free) ----------------
__device__ float g_hs[(size_t)B_ * S_ * H_];   // (B, S, H)

// ---------------- PTX helpers ----------------
__device__ __forceinline__ void ffma2(ull& acc, ull a, ull b) {
    asm("fma.rn.f32x2 %0, %1, %2, %0;" : "+l"(acc) : "l"(a), "l"(b));
}
__device__ __forceinline__ ull splat2(float w) {
    ull r; asm("mov.b64 %0, {%1, %1};" : "=l"(r) : "f"(w)); return r;
}
__device__ __forceinline__ ull fadd2(ull a, ull b) {
    ull r; asm("add.rn.f32x2 %0, %1, %2;" : "=l"(r) : "l"(a), "l"(b)); return r;
}
__device__ __forceinline__ ull f2u(float2 f) {
    ull v; asm("mov.b64 %0, {%1, %2};" : "=l"(v) : "f"(f.x), "f"(f.y)); return v;
}
__device__ __forceinline__ uint32_t smem_u32(const void* p) {
    return (uint32_t)__cvta_generic_to_shared(p);
}
__device__ __forceinline__ uint32_t mapa_rank(uint32_t addr, uint32_t rank) {
    uint32_t r;
    asm("mapa.shared::cluster.u32 %0, %1, %2;" : "=r"(r) : "r"(addr), "r"(rank));
    return r;
}
__device__ __forceinline__ void st_cluster_f32(uint32_t addr, float v) {
    asm volatile("st.shared::cluster.f32 [%0], %1;" :: "r"(addr), "f"(v) : "memory");
}
#define CLUSTER_ARRIVE() asm volatile("barrier.cluster.arrive.aligned;" ::: "memory")
#define CLUSTER_WAIT()   asm volatile("barrier.cluster.wait.aligned;"   ::: "memory")

__device__ __forceinline__ float sigf(float x) {
    return __fdividef(1.0f, 1.0f + __expf(-x));
}
__device__ __forceinline__ float tanhf_(float x) {
    float e = __expf(2.0f * x);
    return 1.0f - __fdividef(2.0f, e + 1.0f);
}

// ---------------- scan smem ----------------
struct ScanSM {
    float Wout[192][64];    // k<64: Wx_out ; else Wh_out   (48 KB)
    float Win[256][64];     // k<128: Wx_in ; else Wh_in    (64 KB)
    float actA[192][8];     // [k][b]  k<64: xt ; else h    (6 KB)
    float actB[256][8];     // [k][b]  k<128: x_in ; else h_in (8 KB)
    ull   red[8][32][10];   // [ksplit][colpair][b(8)+pad]  (20 KB)
    float xhbuf[256];       // x_in then h_in payload
    float hbuf2[128];       // h payload
    float bo[64];
    float bi[64];
};

// GEMM over KW k-values. cols 8cg..8cg+7, batches 2bp,2bp+1.
// acc[j]   = cols(8cg+2j,8cg+2j+1) x batch 2bp
// acc[j+4] = same cols x batch 2bp+1
template<int KW>
__device__ __forceinline__ void gemm_ks(const float* __restrict__ wp,
                                        const float* __restrict__ ap, ull acc[8]) {
#pragma unroll 8
    for (int k = 0; k < KW; ++k) {
        ulonglong2 w01 = *reinterpret_cast<const ulonglong2*>(wp);
        ulonglong2 w23 = *reinterpret_cast<const ulonglong2*>(wp + 4);
        float2 a = *reinterpret_cast<const float2*>(ap);
        wp += 64; ap += 8;
        ull s0 = splat2(a.x), s1 = splat2(a.y);
        ffma2(acc[0], w01.x, s0); ffma2(acc[1], w01.y, s0);
        ffma2(acc[2], w23.x, s0); ffma2(acc[3], w23.y, s0);
        ffma2(acc[4], w01.x, s1); ffma2(acc[5], w01.y, s1);
        ffma2(acc[6], w23.x, s1); ffma2(acc[7], w23.y, s1);
    }
}

// fused reduce: gate value for local col lc = g*16+c, batch b
__device__ __forceinline__ float reduce_gate(const ScanSM& sm, const float* bias,
                                             int g, int c, int b) {
    float v = bias[g * 16 + c];
    const float* fp = reinterpret_cast<const float*>(&sm.red[0][g * 8 + (c >> 1)][b]) + (c & 1);
#pragma unroll
    for (int s2 = 0; s2 < 8; ++s2) { v += *fp; fp += 640; }   // 640 floats = 2560B per ksplit
    return v;
}

__global__ void __launch_bounds__(256, 1) __cluster_dims__(8, 1, 1)
scan_kernel(const float* __restrict__ x,
            const float* __restrict__ Wx_out, const float* __restrict__ Wh_out,
            const float* __restrict__ b_out,
            const float* __restrict__ Wx_in, const float* __restrict__ Wh_in,
            const float* __restrict__ b_in)
{
    extern __shared__ char smraw[];
    ScanSM& sm = *reinterpret_cast<ScanSM*>(smraw);

    const int tid  = threadIdx.x;
    const int rank = blockIdx.x & 7;
    const int bg   = blockIdx.x >> 3;

    const int s  = tid >> 5;          // ksplit / warp id
    const int cg = tid & 7;           // col group: cols 8cg..8cg+7
    const int bp = (tid & 31) >> 3;   // batch pair: 2bp, 2bp+1

    // weight slices (local col lc -> global gate col)
    for (int idx = tid; idx < 192 * 64; idx += 256) {
        int k = idx >> 6, lc = idx & 63;
        int gc = ((lc >> 4) << 7) + (rank << 4) + (lc & 15);
        sm.Wout[k][lc] = (k < 64) ? Wx_out[k * G4_ + gc] : Wh_out[(k - 64) * G4_ + gc];
    }
    for (int idx = tid; idx < 256 * 64; idx += 256) {
        int k = idx >> 6, lc = idx & 63;
        int gc = ((lc >> 4) << 7) + (rank << 4) + (lc & 15);
        sm.Win[k][lc] = (k < 128) ? Wx_in[k * G4_ + gc] : Wh_in[(k - 128) * G4_ + gc];
    }
    if (tid < 64) {
        int gc = ((tid >> 4) << 7) + (rank << 4) + (tid & 15);
        sm.bo[tid] = b_out[gc];
        sm.bi[tid] = b_in[gc];
    }
    // init actA: x(0) + h = 0
    {
        int bb = tid >> 6, i = tid & 63;
        sm.actA[i][bb]     = x[((size_t)(bg * 8 + bb) * I_ + i) * S_];
        sm.actA[i][bb + 4] = x[((size_t)(bg * 8 + bb + 4) * I_ + i) * S_];
    }
    for (int idx = tid; idx < 128 * 8; idx += 256)
        sm.actA[64 + (idx >> 3)][idx & 7] = 0.0f;

    // cluster-mapped bases
    const uint32_t mybase  = smem_u32(&sm);
    const uint32_t offActA = smem_u32(&sm.actA[0][0]) - mybase;
    const uint32_t offActB = smem_u32(&sm.actB[0][0]) - mybase;
    uint32_t rb[8];
#pragma unroll
    for (int r = 0; r < 8; ++r) rb[r] = mapa_rank(mybase, (uint32_t)r);

    // nonlin thread mapping (tid < 128): col c, batch b
    const int nc = tid >> 3;      // 0..15 (valid when tid<128)
    const int nb = tid & 7;
    float cO = 0.0f, cN = 0.0f, oG = 0.0f;

    // push-A mapping: value idx = tid (which*128 + c*8 + b)
    const uint32_t offPA = offActB +
        (uint32_t)(((((tid >> 7) << 7) + (rank << 4) + ((tid >> 3) & 15)) * 8 + (tid & 7)) * 4);
    // push-B mapping: idx = tid&127, ranks (tid>>7)*4 ..+3
    const uint32_t offPB = offActA +
        (uint32_t)(((64 + (rank << 4) + ((tid & 127) >> 3)) * 8 + (tid & 7)) * 4);
    const int rB0 = (tid >> 7) * 4;

    const float* WA = &sm.Wout[s * 24][cg * 8];
    const float* AA = &sm.actA[s * 24][bp * 2];
    const float* WB = &sm.Win[s * 32][cg * 8];
    const float* AB = &sm.actB[s * 32][bp * 2];

    CLUSTER_ARRIVE();   // init done (weights, actA, biases)

#pragma unroll 1
    for (int t = 0; t < S_; ++t) {
        CLUSTER_WAIT();                 // actA (h + xt) ready cluster-wide

        // ===== phase A: outer gates =====
        ull acc[8] = {0, 0, 0, 0, 0, 0, 0, 0};
        gemm_ks<24>(WA, AA, acc);
#pragma unroll
        for (int j = 0; j < 4; ++j) {
            ulonglong2 v; v.x = acc[j]; v.y = acc[j + 4];
            *reinterpret_cast<ulonglong2*>(&sm.red[s][cg * 4 + j][2 * bp]) = v;
        }
        __syncthreads();

        if (tid < 128) {                // fused reduce + nonlin A
            float gi = reduce_gate(sm, sm.bo, 0, nc, nb);
            float gf = reduce_gate(sm, sm.bo, 1, nc, nb);
            float go = reduce_gate(sm, sm.bo, 2, nc, nb);
            float gg = reduce_gate(sm, sm.bo, 3, nc, nb);
            float iv = sigf(gi), fv = sigf(gf);
            oG = sigf(go);
            float gv = tanhf_(gg);
            sm.xhbuf[tid]       = iv * gv;     // x_in
            sm.xhbuf[128 + tid] = fv * cO;     // h_in
        }
        __syncthreads();

        {   // push x_in/h_in to all 8 CTAs' actB
            float v = sm.xhbuf[tid];
#pragma unroll
            for (int r = 0; r < 8; ++r) st_cluster_f32(rb[r] + offPA, v);
        }
        CLUSTER_ARRIVE();               // actB pushes released

        // x prefetch for t+1 (in barrier shadow)
        float x0 = 0.0f, x1 = 0.0f;
        if (t + 1 < S_) {
            int bb = tid >> 6, i = tid & 63;
            x0 = x[((size_t)(bg * 8 + bb) * I_ + i) * S_ + (t + 1)];
            x1 = x[((size_t)(bg * 8 + bb + 4) * I_ + i) * S_ + (t + 1)];
        }
        CLUSTER_WAIT();                 // actB ready cluster-wide

        // ===== phase B: inner gates =====
#pragma unroll
        for (int j = 0; j < 8; ++j) acc[j] = 0;
        gemm_ks<32>(WB, AB, acc);
#pragma unroll
        for (int j = 0; j < 4; ++j) {
            ulonglong2 v; v.x = acc[j]; v.y = acc[j + 4];
            *reinterpret_cast<ulonglong2*>(&sm.red[s][cg * 4 + j][2 * bp]) = v;
        }
        __syncthreads();

        if (tid < 128) {                // fused reduce + nonlin B + state update
            float gi = reduce_gate(sm, sm.bi, 0, nc, nb);
            float gf = reduce_gate(sm, sm.bi, 1, nc, nb);
            float go = reduce_gate(sm, sm.bi, 2, nc, nb);
            float gg = reduce_gate(sm, sm.bi, 3, nc, nb);
            float ii = sigf(gi), fi = sigf(gf), oi = sigf(go), tg = tanhf_(gg);
            cN = fi * cN + ii * tg;
            cO = oi * tanhf_(cN);
            float h = oG * tanhf_(cO);
            sm.hbuf2[tid] = h;
            g_hs[((size_t)(bg * 8 + nb) * S_ + t) * H_ + (rank << 4) + nc] = h;
        }
        __syncthreads();

        {   // push h to all 8 CTAs' actA h-region (4 ranks per thread)
            float v = sm.hbuf2[tid & 127];
#pragma unroll
            for (int r = 0; r < 4; ++r) st_cluster_f32(rb[rB0 + r] + offPB, v);
        }
        {   // store prefetched x(t+1) locally
            int bb = tid >> 6, i = tid & 63;
            sm.actA[i][bb]     = x0;
            sm.actA[i][bb + 4] = x1;
        }
        CLUSTER_ARRIVE();               // actA pushes + x released
    }
    CLUSTER_WAIT();                     // drain final generation before exit
}

// ---------------- final projection ----------------
struct ProjSM {
    float Wt[128][66];
    float hsS[64][128];
};

__global__ void __launch_bounds__(256, 1)
proj_kernel(const float* __restrict__ W_lin, const float* __restrict__ b_lin,
            float* __restrict__ out)
{
    extern __shared__ char smraw[];
    ProjSM& sm = *reinterpret_cast<ProjSM*>(smraw);
    const int tid = threadIdx.x;
    const size_t row0 = (size_t)blockIdx.x * 64;

    for (int idx = tid; idx < 64 * 128; idx += 256) {
        int oc = idx >> 7, k = idx & 127;
        sm.Wt[k][oc] = W_lin[oc * H_ + k];
    }
    for (int idx = tid; idx < 64 * 128; idx += 256) {
        int rl = idx >> 7, k = idx & 127;
        sm.hsS[rl][k] = g_hs[(row0 + rl) * H_ + k];
    }
    __syncthreads();

    const int cp = tid & 31;
    const int rg = tid >> 5;
    ull acc[8] = {0, 0, 0, 0, 0, 0, 0, 0};

#pragma unroll 4
    for (int k = 0; k < 128; ++k) {
        ull w2 = *reinterpret_cast<const ull*>(&sm.Wt[k][cp * 2]);
#pragma unroll
        for (int rr = 0; rr < 8; ++rr) {
            ull a = splat2(sm.hsS[rg * 8 + rr][k]);
            ffma2(acc[rr], w2, a);
        }
    }
    ull b2 = f2u(make_float2(b_lin[cp * 2], b_lin[cp * 2 + 1]));
#pragma unroll
    for (int rr = 0; rr < 8; ++rr) {
        ull r = fadd2(acc[rr], b2);
        *reinterpret_cast<ull*>(&out[(row0 + rg * 8 + rr) * O_ + cp * 2]) = r;
    }
}

// ---------------- host launcher ----------------
extern "C" void kernel_launch(void* const* d_in, const int* in_sizes, int n_in,
                              void* d_out, int out_size) {
    const float* x      = (const float*)d_in[0];
    const float* Wx_out = (const float*)d_in[1];
    const float* Wh_out = (const float*)d_in[2];
    const float* b_out  = (const float*)d_in[3];
    const float* Wx_in  = (const float*)d_in[4];
    const float* Wh_in  = (const float*)d_in[5];
    const float* b_in   = (const float*)d_in[6];
    const float* W_lin  = (const float*)d_in[7];
    const float* b_lin  = (const float*)d_in[8];
    float* out = (float*)d_out;

    cudaFuncSetAttribute(scan_kernel, cudaFuncAttributeMaxDynamicSharedMemorySize,
                         (int)sizeof(ScanSM));
    cudaFuncSetAttribute(proj_kernel, cudaFuncAttributeMaxDynamicSharedMemorySize,
                         (int)sizeof(ProjSM));

    scan_kernel<<<128, 256, sizeof(ScanSM)>>>(x, Wx_out, Wh_out, b_out,
                                              Wx_in, Wh_in, b_in);
    proj_kernel<<<(B_ * S_) / 64, 256, sizeof(ProjSM)>>>(W_lin, b_lin, out);
}